// round 5
// baseline (speedup 1.0000x reference)
#include <cuda_runtime.h>
#include <cstdint>

#define NDRUG 100000
#define NPROT 100000
#define NN    100000            // nodes per type (drug == prot count)
#define NEMAX 800000
#define DIM   128
#define SA    132   // smem row stride in floats (conflict-free for quad patterns)

// ---------------- scratch (no runtime allocation allowed) ----------------
__device__ float g_hd1[(size_t)NDRUG * DIM];
__device__ float g_hp1[(size_t)NPROT * DIM];
__device__ float g_hd2[(size_t)NDRUG * DIM];
__device__ float g_hp2[(size_t)NPROT * DIM];
// 6 rsqrt-degree arrays: [0]=ddi_out [1]=ddi_in [2]=pdi_out [3]=pdi_in [4]=ppi_out [5]=ppi_in
__device__ float g_rs[(size_t)6 * NN];
// transposed + tf32-rounded weights: 9 matrices of [n][k]
__device__ float g_Wt[(size_t)9 * DIM * DIM];
// CSR (by dst) per relation
__device__ int g_indptr[3 * (NN + 1)];
__device__ int g_cursor[3 * NN];
__device__ int g_eidx[3 * NEMAX];
__device__ int g_bsum[256];

// ---------------- degree kernels ----------------
// one pass per relation: count src (out-deg) and dst (in-deg)
__global__ void count2_kernel(const int* __restrict__ src, const int* __restrict__ dst,
                              float* __restrict__ cs, float* __restrict__ cd, int n) {
    int i = blockIdx.x * blockDim.x + threadIdx.x;
    if (i < n) {
        atomicAdd(&cs[src[i]], 1.0f);
        atomicAdd(&cd[dst[i]], 1.0f);
    }
}
__global__ void rsqrt_kernel(float* __restrict__ p, int n) {
    int i = blockIdx.x * blockDim.x + threadIdx.x;
    if (i < n) p[i] = rsqrtf(fmaxf(p[i], 1.0f));
}
// transpose 3 stacked [128x128] weight matrices to [n][k], rounding to tf32 once
__global__ void transpose_w(const float* __restrict__ W, float* __restrict__ Wt) {
    int i = blockIdx.x * blockDim.x + threadIdx.x;
    if (i < 3 * DIM * DIM) {
        int rel = i >> 14, rem = i & 16383;
        int k = rem >> 7, n = rem & 127;
        float v = W[i];
        uint32_t u;
        asm("cvt.rna.tf32.f32 %0, %1;" : "=r"(u) : "f"(v));
        Wt[(rel << 14) + (n << 7) + k] = __uint_as_float(u);
    }
}

// ---------------- exclusive scan (float counts -> int indptr) ----------------
__global__ void scan1(const float* __restrict__ cnt, int* __restrict__ excl,
                      int* __restrict__ bsum, int n) {
    __shared__ int sm2[1024];
    int tid = threadIdx.x;
    int i = blockIdx.x * 1024 + tid;
    int v = (i < n) ? (int)cnt[i] : 0;
    sm2[tid] = v;
    __syncthreads();
#pragma unroll
    for (int off = 1; off < 1024; off <<= 1) {
        int t2 = (tid >= off) ? sm2[tid - off] : 0;
        __syncthreads();
        sm2[tid] += t2;
        __syncthreads();
    }
    if (i < n) excl[i] = sm2[tid] - v;
    if (tid == 1023) bsum[blockIdx.x] = sm2[1023];
}
__global__ void scan2(int* __restrict__ bsum, int nb) {
    __shared__ int sm2[256];
    int tid = threadIdx.x;
    sm2[tid] = (tid < nb) ? bsum[tid] : 0;
    __syncthreads();
#pragma unroll
    for (int off = 1; off < 256; off <<= 1) {
        int t2 = (tid >= off) ? sm2[tid - off] : 0;
        __syncthreads();
        sm2[tid] += t2;
        __syncthreads();
    }
    if (tid < nb) bsum[tid] = sm2[tid];   // inclusive
}
__global__ void scan3(const float* __restrict__ cnt, int* __restrict__ excl,
                      const int* __restrict__ bsum, int n) {
    int i = blockIdx.x * blockDim.x + threadIdx.x;
    if (i < n) {
        int b = i >> 10;
        int off = b ? bsum[b - 1] : 0;
        int e = excl[i] + off;
        excl[i] = e;
        if (i == n - 1) excl[n] = e + (int)cnt[i];
    }
}
__global__ void fill_kernel(const int* __restrict__ src, const int* __restrict__ dst,
                            int* __restrict__ cursor, int* __restrict__ eidx, int nE) {
    int e = blockIdx.x * blockDim.x + threadIdx.x;
    if (e < nE) {
        int p = atomicAdd(&cursor[dst[e]], 1);
        eidx[p] = src[e];
    }
}

// ---------------- fused gather + tf32 mma.sync GEMM ----------------
// out[m,:] = act( gathered_A1[m,:] @ W1 (+ gathered_A2[m,:] @ W2) + b1 (+ b2) )
// gathered_A[m,:] = rs_in[m] * sum_{e in CSR(m)} rs_out[src_e] * h[src_e,:]
__device__ __forceinline__ void mma_tf32(float c[4], const uint32_t a[4], const uint32_t b[2]) {
    asm volatile(
        "mma.sync.aligned.m16n8k8.row.col.f32.tf32.tf32.f32 "
        "{%0,%1,%2,%3}, {%4,%5,%6,%7}, {%8,%9}, {%0,%1,%2,%3};"
        : "+f"(c[0]), "+f"(c[1]), "+f"(c[2]), "+f"(c[3])
        : "r"(a[0]), "r"(a[1]), "r"(a[2]), "r"(a[3]), "r"(b[0]), "r"(b[1]));
}

template<bool RELU, bool TWO>
__global__ void __launch_bounds__(256)
fused_mma(const float* __restrict__ h1, const int* __restrict__ ip1,
          const int* __restrict__ ei1, const float* __restrict__ rso1,
          const float* __restrict__ rsi1,
          const float* __restrict__ h2, const int* __restrict__ ip2,
          const int* __restrict__ ei2, const float* __restrict__ rso2,
          const float* __restrict__ rsi2,
          const float* __restrict__ Wt1, const float* __restrict__ Wt2,
          const float* __restrict__ b1, const float* __restrict__ b2,
          float* __restrict__ out, int nrows) {
    extern __shared__ float sm[];
    float* As = sm;               // [128][SA]
    float* Ws = sm + 128 * SA;    // [128][SA]

    const int t = threadIdx.x;
    const int lane = t & 31, wid = t >> 5;
    const int wm = wid >> 2, wn = wid & 3;      // 2 x 4 warp grid
    const int row0 = blockIdx.x * 128;
    const int qid = lane >> 2, qtl = lane & 3;  // quad id / thread-in-quad

    float acc[4][4][4];
#pragma unroll
    for (int mi = 0; mi < 4; mi++)
#pragma unroll
        for (int ni = 0; ni < 4; ni++)
#pragma unroll
            for (int j = 0; j < 4; j++) acc[mi][ni][j] = 0.0f;

    const int nsrc = TWO ? 2 : 1;
    for (int s = 0; s < nsrc; s++) {
        const float* h   = s ? h2   : h1;
        const int*   ip  = s ? ip2  : ip1;
        const int*   ei  = s ? ei2  : ei1;
        const float* rso = s ? rso2 : rso1;
        const float* rsi = s ? rsi2 : rsi1;
        const float* Wt  = s ? Wt2  : Wt1;
        if (s) __syncthreads();   // prior mma reads done before smem overwrite

        // Gather A tile directly into smem: warp wid handles rows wid*16..wid*16+15.
        for (int rr = 0; rr < 16; rr++) {
            int r = wid * 16 + rr;
            int row = row0 + r;
            float4 a4 = make_float4(0.f, 0.f, 0.f, 0.f);
            if (row < nrows) {
                int s0 = __ldg(ip + row), s1 = __ldg(ip + row + 1);
                for (int base = s0; base < s1; base += 32) {
                    int m = min(32, s1 - base);
                    int se = (lane < m) ? __ldg(ei + base + lane) : 0;
                    for (int i = 0; i < m; i++) {
                        int sn = __shfl_sync(0xFFFFFFFFu, se, i);
                        float sc = __ldg(rso + sn);
                        float4 v = __ldg(reinterpret_cast<const float4*>(h + (size_t)sn * DIM) + lane);
                        a4.x += sc * v.x; a4.y += sc * v.y; a4.z += sc * v.z; a4.w += sc * v.w;
                    }
                }
                float ri = __ldg(rsi + row);
                a4.x *= ri; a4.y *= ri; a4.z *= ri; a4.w *= ri;
            }
            uint4 u;
            asm("cvt.rna.tf32.f32 %0, %1;" : "=r"(u.x) : "f"(a4.x));
            asm("cvt.rna.tf32.f32 %0, %1;" : "=r"(u.y) : "f"(a4.y));
            asm("cvt.rna.tf32.f32 %0, %1;" : "=r"(u.z) : "f"(a4.z));
            asm("cvt.rna.tf32.f32 %0, %1;" : "=r"(u.w) : "f"(a4.w));
            *reinterpret_cast<uint4*>(&As[r * SA + lane * 4]) = u;
        }
        // W tile [n][k] (already tf32-rounded)
#pragma unroll
        for (int i = 0; i < 16; i++) {
            int e = t + 256 * i;
            int r = e >> 5, c4 = e & 31;
            float4 v = __ldg(reinterpret_cast<const float4*>(Wt + (size_t)r * DIM) + c4);
            *reinterpret_cast<float4*>(&Ws[r * SA + c4 * 4]) = v;
        }
        __syncthreads();

        // 16 k-steps of m16n8k8
#pragma unroll
        for (int ks = 0; ks < 16; ks++) {
            const int k0 = ks * 8;
            uint32_t a[4][4];
#pragma unroll
            for (int mi = 0; mi < 4; mi++) {
                const float* p = &As[(wm * 64 + mi * 16 + qid) * SA + k0 + qtl];
                a[mi][0] = __float_as_uint(p[0]);
                a[mi][1] = __float_as_uint(p[8 * SA]);
                a[mi][2] = __float_as_uint(p[4]);
                a[mi][3] = __float_as_uint(p[8 * SA + 4]);
            }
            uint32_t b[4][2];
#pragma unroll
            for (int ni = 0; ni < 4; ni++) {
                const float* p = &Ws[(wn * 32 + ni * 8 + qid) * SA + k0 + qtl];
                b[ni][0] = __float_as_uint(p[0]);
                b[ni][1] = __float_as_uint(p[4]);
            }
#pragma unroll
            for (int mi = 0; mi < 4; mi++)
#pragma unroll
                for (int ni = 0; ni < 4; ni++)
                    mma_tf32(acc[mi][ni], a[mi], b[ni]);
        }
    }

    // Epilogue: bias (+bias2), optional ReLU, float2 stores
#pragma unroll
    for (int ni = 0; ni < 4; ni++) {
        int col = wn * 32 + ni * 8 + qtl * 2;
        float bb0 = __ldg(b1 + col)     + (TWO ? __ldg(b2 + col)     : 0.0f);
        float bb1 = __ldg(b1 + col + 1) + (TWO ? __ldg(b2 + col + 1) : 0.0f);
#pragma unroll
        for (int mi = 0; mi < 4; mi++) {
            int r0 = row0 + wm * 64 + mi * 16 + qid;
            if (r0 < nrows) {
                float2 o;
                o.x = acc[mi][ni][0] + bb0;
                o.y = acc[mi][ni][1] + bb1;
                if (RELU) { o.x = fmaxf(o.x, 0.0f); o.y = fmaxf(o.y, 0.0f); }
                *reinterpret_cast<float2*>(out + (size_t)r0 * DIM + col) = o;
            }
            int r1 = r0 + 8;
            if (r1 < nrows) {
                float2 o;
                o.x = acc[mi][ni][2] + bb0;
                o.y = acc[mi][ni][3] + bb1;
                if (RELU) { o.x = fmaxf(o.x, 0.0f); o.y = fmaxf(o.y, 0.0f); }
                *reinterpret_cast<float2*>(out + (size_t)r1 * DIM + col) = o;
            }
        }
    }
}

// ---------------- host orchestration ----------------
static const size_t GEMM_SMEM = 2u * 128u * SA * sizeof(float);  // 135168 B

static void run_layer(const float* hd_in, const float* hp_in,
                      float* hd_out, float* hp_out,
                      const float* Wt /*3x[n][k]*/, const float* b, bool relu,
                      int* indptr, int* eidx, float* rs) {
    const int gblocks = (NDRUG + 127) / 128;
    const int* ip_ddi = indptr + 0 * (NN + 1);
    const int* ip_pdi = indptr + 1 * (NN + 1);
    const int* ip_ppi = indptr + 2 * (NN + 1);
    const int* ei_ddi = eidx + 0 * NEMAX;
    const int* ei_pdi = eidx + 1 * NEMAX;
    const int* ei_ppi = eidx + 2 * NEMAX;

    if (relu) {
        fused_mma<true, true><<<gblocks, 256, GEMM_SMEM>>>(
            hd_in, ip_ddi, ei_ddi, rs + 0 * NN, rs + 1 * NN,
            hp_in, ip_pdi, ei_pdi, rs + 2 * NN, rs + 3 * NN,
            Wt + 0 * DIM * DIM, Wt + 1 * DIM * DIM, b + 0 * DIM, b + 1 * DIM,
            hd_out, NDRUG);
        fused_mma<true, false><<<gblocks, 256, GEMM_SMEM>>>(
            hp_in, ip_ppi, ei_ppi, rs + 4 * NN, rs + 5 * NN,
            nullptr, nullptr, nullptr, nullptr, nullptr,
            Wt + 2 * DIM * DIM, nullptr, b + 2 * DIM, nullptr,
            hp_out, NPROT);
    } else {
        fused_mma<false, true><<<gblocks, 256, GEMM_SMEM>>>(
            hd_in, ip_ddi, ei_ddi, rs + 0 * NN, rs + 1 * NN,
            hp_in, ip_pdi, ei_pdi, rs + 2 * NN, rs + 3 * NN,
            Wt + 0 * DIM * DIM, Wt + 1 * DIM * DIM, b + 0 * DIM, b + 1 * DIM,
            hd_out, NDRUG);
        fused_mma<false, false><<<gblocks, 256, GEMM_SMEM>>>(
            hp_in, ip_ppi, ei_ppi, rs + 4 * NN, rs + 5 * NN,
            nullptr, nullptr, nullptr, nullptr, nullptr,
            Wt + 2 * DIM * DIM, nullptr, b + 2 * DIM, nullptr,
            hp_out, NPROT);
    }
}

extern "C" void kernel_launch(void* const* d_in, const int* in_sizes, int n_in,
                              void* d_out, int out_size) {
    const float* hd0   = (const float*)d_in[0];
    const float* hp0   = (const float*)d_in[1];
    const int*   ddi_s = (const int*)d_in[2];
    const int*   ddi_d = (const int*)d_in[3];
    const int*   pdi_s = (const int*)d_in[4];
    const int*   pdi_d = (const int*)d_in[5];
    const int*   ppi_s = (const int*)d_in[6];
    const int*   ppi_d = (const int*)d_in[7];
    const float* W1 = (const float*)d_in[8];
    const float* b1 = (const float*)d_in[9];
    const float* W2 = (const float*)d_in[10];
    const float* b2 = (const float*)d_in[11];
    const float* W3 = (const float*)d_in[12];
    const float* b3 = (const float*)d_in[13];

    const int nE_ddi = in_sizes[2];
    const int nE_pdi = in_sizes[4];
    const int nE_ppi = in_sizes[6];

    cudaFuncSetAttribute(fused_mma<true, true>,   cudaFuncAttributeMaxDynamicSharedMemorySize, (int)GEMM_SMEM);
    cudaFuncSetAttribute(fused_mma<true, false>,  cudaFuncAttributeMaxDynamicSharedMemorySize, (int)GEMM_SMEM);
    cudaFuncSetAttribute(fused_mma<false, true>,  cudaFuncAttributeMaxDynamicSharedMemorySize, (int)GEMM_SMEM);
    cudaFuncSetAttribute(fused_mma<false, false>, cudaFuncAttributeMaxDynamicSharedMemorySize, (int)GEMM_SMEM);

    float *hd1, *hp1, *hd2, *hp2, *rs, *wt;
    int *indptr, *cursor, *eidx, *bsum;
    cudaGetSymbolAddress((void**)&hd1, g_hd1);
    cudaGetSymbolAddress((void**)&hp1, g_hp1);
    cudaGetSymbolAddress((void**)&hd2, g_hd2);
    cudaGetSymbolAddress((void**)&hp2, g_hp2);
    cudaGetSymbolAddress((void**)&rs, g_rs);
    cudaGetSymbolAddress((void**)&wt, g_Wt);
    cudaGetSymbolAddress((void**)&indptr, g_indptr);
    cudaGetSymbolAddress((void**)&cursor, g_cursor);
    cudaGetSymbolAddress((void**)&eidx, g_eidx);
    cudaGetSymbolAddress((void**)&bsum, g_bsum);

    // transposed+rounded weights
    {
        int n = 3 * DIM * DIM, blks = (n + 255) / 256;
        transpose_w<<<blks, 256>>>(W1, wt + 0 * 3 * DIM * DIM);
        transpose_w<<<blks, 256>>>(W2, wt + 1 * 3 * DIM * DIM);
        transpose_w<<<blks, 256>>>(W3, wt + 2 * 3 * DIM * DIM);
    }

    // degree histograms (float counts): one pass per relation
    cudaMemsetAsync(rs, 0, (size_t)6 * NN * sizeof(float), 0);
    count2_kernel<<<(nE_ddi + 255) / 256, 256>>>(ddi_s, ddi_d, rs + 0 * NN, rs + 1 * NN, nE_ddi);
    count2_kernel<<<(nE_pdi + 255) / 256, 256>>>(pdi_s, pdi_d, rs + 2 * NN, rs + 3 * NN, nE_pdi);
    count2_kernel<<<(nE_ppi + 255) / 256, 256>>>(ppi_s, ppi_d, rs + 4 * NN, rs + 5 * NN, nE_ppi);

    // CSR build per relation (from raw float in-degree counts, BEFORE rsqrt)
    const int nb = (NN + 1023) / 1024;
    const int tb = (NN + 255) / 256;
    scan1<<<nb, 1024>>>(rs + 1 * NN, indptr + 0 * (NN + 1), bsum, NN);
    scan2<<<1, 256>>>(bsum, nb);
    scan3<<<tb, 256>>>(rs + 1 * NN, indptr + 0 * (NN + 1), bsum, NN);
    scan1<<<nb, 1024>>>(rs + 3 * NN, indptr + 1 * (NN + 1), bsum, NN);
    scan2<<<1, 256>>>(bsum, nb);
    scan3<<<tb, 256>>>(rs + 3 * NN, indptr + 1 * (NN + 1), bsum, NN);
    scan1<<<nb, 1024>>>(rs + 5 * NN, indptr + 2 * (NN + 1), bsum, NN);
    scan2<<<1, 256>>>(bsum, nb);
    scan3<<<tb, 256>>>(rs + 5 * NN, indptr + 2 * (NN + 1), bsum, NN);

    cudaMemcpyAsync(cursor + 0 * NN, indptr + 0 * (NN + 1), NN * sizeof(int), cudaMemcpyDeviceToDevice, 0);
    cudaMemcpyAsync(cursor + 1 * NN, indptr + 1 * (NN + 1), NN * sizeof(int), cudaMemcpyDeviceToDevice, 0);
    cudaMemcpyAsync(cursor + 2 * NN, indptr + 2 * (NN + 1), NN * sizeof(int), cudaMemcpyDeviceToDevice, 0);

    fill_kernel<<<(nE_ddi + 255) / 256, 256>>>(ddi_s, ddi_d, cursor + 0 * NN, eidx + 0 * NEMAX, nE_ddi);
    fill_kernel<<<(nE_pdi + 255) / 256, 256>>>(pdi_s, pdi_d, cursor + 1 * NN, eidx + 1 * NEMAX, nE_pdi);
    fill_kernel<<<(nE_ppi + 255) / 256, 256>>>(ppi_s, ppi_d, cursor + 2 * NN, eidx + 2 * NEMAX, nE_ppi);

    // counts -> rsqrt(max(deg,1))  (after scans have consumed raw counts)
    rsqrt_kernel<<<(6 * NN + 255) / 256, 256>>>(rs, 6 * NN);

    float* outd = (float*)d_out;
    float* outp = outd + (size_t)NDRUG * DIM;

    run_layer(hd0, hp0, hd1, hp1, wt + 0 * 3 * DIM * DIM, b1, true, indptr, eidx, rs);
    run_layer(hd1, hp1, hd2, hp2, wt + 1 * 3 * DIM * DIM, b2, true, indptr, eidx, rs);
    run_layer(hd2, hp2, outd, outp, wt + 2 * 3 * DIM * DIM, b3, false, indptr, eidx, rs);
}

// round 6
// speedup vs baseline: 3.0434x; 3.0434x over previous
#include <cuda_runtime.h>
#include <cstdint>

#define NDRUG 100000
#define NPROT 100000
#define NN    100000            // nodes per type (drug == prot count)
#define NEMAX 800000
#define DIM   128
#define SA    132   // smem row stride in floats (conflict-free for quad patterns)

// ---------------- scratch (no runtime allocation allowed) ----------------
__device__ float g_hd1[(size_t)NDRUG * DIM];
__device__ float g_hp1[(size_t)NPROT * DIM];
__device__ float g_hd2[(size_t)NDRUG * DIM];
__device__ float g_hp2[(size_t)NPROT * DIM];
__device__ float g_agg1[(size_t)NDRUG * DIM];   // DDI aggregate (drug dst)
__device__ float g_agg2[(size_t)NDRUG * DIM];   // PDI aggregate (drug dst)
__device__ float g_aggp[(size_t)NPROT * DIM];   // PPI aggregate (protein dst)
// 6 rsqrt-degree arrays: [0]=ddi_out [1]=ddi_in [2]=pdi_out [3]=pdi_in [4]=ppi_out [5]=ppi_in
__device__ float g_rs[(size_t)6 * NN];
// transposed + tf32-rounded weights: 9 matrices of [n][k]
__device__ float g_Wt[(size_t)9 * DIM * DIM];
// CSR (by dst) per relation
__device__ int g_indptr[3 * (NN + 1)];
__device__ int g_cursor[3 * NN];
__device__ int g_eidx[3 * NEMAX];
__device__ int g_bsum[3 * 128];

// ---------------- degree kernels ----------------
__global__ void count2_kernel(const int* __restrict__ src, const int* __restrict__ dst,
                              float* __restrict__ cs, float* __restrict__ cd, int n) {
    int i = blockIdx.x * blockDim.x + threadIdx.x;
    if (i < n) {
        atomicAdd(&cs[src[i]], 1.0f);
        atomicAdd(&cd[dst[i]], 1.0f);
    }
}
__global__ void rsqrt_kernel(float* __restrict__ p, int n) {
    int i = blockIdx.x * blockDim.x + threadIdx.x;
    if (i < n) p[i] = rsqrtf(fmaxf(p[i], 1.0f));
}
// transpose all 9 [128x128] weight matrices to [n][k], rounding to tf32 once
__global__ void transpose_w9(const float* __restrict__ Wa, const float* __restrict__ Wb,
                             const float* __restrict__ Wc, float* __restrict__ Wt) {
    int i = blockIdx.x * blockDim.x + threadIdx.x;
    if (i < 9 * DIM * DIM) {
        int grp = i / (3 * DIM * DIM);          // 0,1,2 -> W1,W2,W3
        int rem3 = i - grp * 3 * DIM * DIM;
        const float* W = grp == 0 ? Wa : (grp == 1 ? Wb : Wc);
        int rel = rem3 >> 14, rem = rem3 & 16383;
        int k = rem >> 7, n = rem & 127;
        float v = W[(rel << 14) + (k << 7) + n];
        uint32_t u;
        asm("cvt.rna.tf32.f32 %0, %1;" : "=r"(u) : "f"(v));
        Wt[i - rem + (n << 7) + k] = __uint_as_float(u);   // i-rem = base of [grp][rel]
    }
}

// ---------------- exclusive scan (float counts -> int indptr), batched over 3 relations ----------------
// counts for relation rel live at cnt_base + (2*rel+1)*NN; indptr at rel*(NN+1)
__global__ void scan1(const float* __restrict__ rs, int* __restrict__ indptr,
                      int* __restrict__ bsum) {
    __shared__ int sm2[1024];
    const int rel = blockIdx.y;
    const float* cnt = rs + (size_t)(2 * rel + 1) * NN;
    int* excl = indptr + rel * (NN + 1);
    int tid = threadIdx.x;
    int i = blockIdx.x * 1024 + tid;
    int v = (i < NN) ? (int)cnt[i] : 0;
    sm2[tid] = v;
    __syncthreads();
#pragma unroll
    for (int off = 1; off < 1024; off <<= 1) {
        int t2 = (tid >= off) ? sm2[tid - off] : 0;
        __syncthreads();
        sm2[tid] += t2;
        __syncthreads();
    }
    if (i < NN) excl[i] = sm2[tid] - v;
    if (tid == 1023) bsum[rel * 128 + blockIdx.x] = sm2[1023];
}
__global__ void scan2(int* __restrict__ bsum, int nb) {
    __shared__ int sm2[256];
    const int rel = blockIdx.x;
    int tid = threadIdx.x;
    sm2[tid] = (tid < nb) ? bsum[rel * 128 + tid] : 0;
    __syncthreads();
#pragma unroll
    for (int off = 1; off < 256; off <<= 1) {
        int t2 = (tid >= off) ? sm2[tid - off] : 0;
        __syncthreads();
        sm2[tid] += t2;
        __syncthreads();
    }
    if (tid < nb) bsum[rel * 128 + tid] = sm2[tid];   // inclusive
}
__global__ void scan3(const float* __restrict__ rs, int* __restrict__ indptr,
                      const int* __restrict__ bsum, int* __restrict__ cursor) {
    const int rel = blockIdx.y;
    const float* cnt = rs + (size_t)(2 * rel + 1) * NN;
    int* excl = indptr + rel * (NN + 1);
    int i = blockIdx.x * blockDim.x + threadIdx.x;
    if (i < NN) {
        int b = i >> 10;
        int off = b ? bsum[rel * 128 + b - 1] : 0;
        int e = excl[i] + off;
        excl[i] = e;
        cursor[rel * NN + i] = e;
        if (i == NN - 1) excl[NN] = e + (int)cnt[i];
    }
}
// batched fill over 3 relations (grid.y = rel)
__global__ void fill3_kernel(const int* __restrict__ s0, const int* __restrict__ d0, int n0,
                             const int* __restrict__ s1, const int* __restrict__ d1, int n1,
                             const int* __restrict__ s2, const int* __restrict__ d2, int n2,
                             int* __restrict__ cursor, int* __restrict__ eidx) {
    const int rel = blockIdx.y;
    const int* src = rel == 0 ? s0 : (rel == 1 ? s1 : s2);
    const int* dst = rel == 0 ? d0 : (rel == 1 ? d1 : d2);
    int nE = rel == 0 ? n0 : (rel == 1 ? n1 : n2);
    int e = blockIdx.x * blockDim.x + threadIdx.x;
    if (e < nE) {
        int p = atomicAdd(&cursor[rel * NN + dst[e]], 1);
        eidx[rel * NEMAX + p] = src[e];
    }
}

// ---------------- CSR gather: agg[d,:] = rs_in[d] * sum_e rs_out[src_e] * h[src_e,:] ----------------
__global__ void __launch_bounds__(256)
gather_kernel(const float* __restrict__ h, const int* __restrict__ indptr,
              const int* __restrict__ eidx, const float* __restrict__ rs_out,
              const float* __restrict__ rs_in, float* __restrict__ agg, int nrows) {
    int w = (blockIdx.x * blockDim.x + threadIdx.x) >> 5;
    int lane = threadIdx.x & 31;
    if (w >= nrows) return;
    int s0 = __ldg(indptr + w), s1 = __ldg(indptr + w + 1);
    float4 acc = make_float4(0.f, 0.f, 0.f, 0.f);
    for (int base = s0; base < s1; base += 32) {
        int m = min(32, s1 - base);
        int se = (lane < m) ? __ldg(eidx + base + lane) : 0;
#pragma unroll 4
        for (int i = 0; i < m; i++) {
            int s = __shfl_sync(0xFFFFFFFFu, se, i);
            float sc = __ldg(rs_out + s);
            float4 v = __ldg(reinterpret_cast<const float4*>(h + (size_t)s * DIM) + lane);
            acc.x += sc * v.x; acc.y += sc * v.y; acc.z += sc * v.z; acc.w += sc * v.w;
        }
    }
    float ri = __ldg(rs_in + w);
    acc.x *= ri; acc.y *= ri; acc.z *= ri; acc.w *= ri;
    reinterpret_cast<float4*>(agg + (size_t)w * DIM)[lane] = acc;
}

// ---------------- tf32 mma.sync GEMM ----------------
// out[m,:] = act( A1[m,:] @ W1 (+ A2[m,:] @ W2) + b1 (+ b2) )   (degree scaling pre-folded)
__device__ __forceinline__ void mma_tf32(float c[4], const uint32_t a[4], const uint32_t b[2]) {
    asm volatile(
        "mma.sync.aligned.m16n8k8.row.col.f32.tf32.tf32.f32 "
        "{%0,%1,%2,%3}, {%4,%5,%6,%7}, {%8,%9}, {%0,%1,%2,%3};"
        : "+f"(c[0]), "+f"(c[1]), "+f"(c[2]), "+f"(c[3])
        : "r"(a[0]), "r"(a[1]), "r"(a[2]), "r"(a[3]), "r"(b[0]), "r"(b[1]));
}

template<bool RELU, bool TWO>
__global__ void __launch_bounds__(256)
gemm_mma(const float* __restrict__ A1, const float* __restrict__ A2,
         const float* __restrict__ Wt1, const float* __restrict__ Wt2,
         const float* __restrict__ b1, const float* __restrict__ b2,
         float* __restrict__ out, int nrows) {
    extern __shared__ float sm[];
    float* As = sm;               // [128][SA]
    float* Ws = sm + 128 * SA;    // [128][SA]

    const int t = threadIdx.x;
    const int lane = t & 31, wid = t >> 5;
    const int wm = wid >> 2, wn = wid & 3;      // 2 x 4 warp grid
    const int row0 = blockIdx.x * 128;
    const int qid = lane >> 2, qtl = lane & 3;  // quad id / thread-in-quad

    float acc[4][4][4];
#pragma unroll
    for (int mi = 0; mi < 4; mi++)
#pragma unroll
        for (int ni = 0; ni < 4; ni++)
#pragma unroll
            for (int j = 0; j < 4; j++) acc[mi][ni][j] = 0.0f;

    const int nsrc = TWO ? 2 : 1;
    for (int s = 0; s < nsrc; s++) {
        const float* A  = s ? A2  : A1;
        const float* Wt = s ? Wt2 : Wt1;
        if (s) __syncthreads();   // prior mma reads done before smem overwrite

        // A tile: round to tf32, zero-pad past nrows
#pragma unroll
        for (int i = 0; i < 16; i++) {
            int e = t + 256 * i;
            int r = e >> 5, c4 = e & 31;
            int row = row0 + r;
            float4 v = make_float4(0.f, 0.f, 0.f, 0.f);
            if (row < nrows)
                v = __ldg(reinterpret_cast<const float4*>(A + (size_t)row * DIM) + c4);
            uint4 u;
            asm("cvt.rna.tf32.f32 %0, %1;" : "=r"(u.x) : "f"(v.x));
            asm("cvt.rna.tf32.f32 %0, %1;" : "=r"(u.y) : "f"(v.y));
            asm("cvt.rna.tf32.f32 %0, %1;" : "=r"(u.z) : "f"(v.z));
            asm("cvt.rna.tf32.f32 %0, %1;" : "=r"(u.w) : "f"(v.w));
            *reinterpret_cast<uint4*>(&As[r * SA + c4 * 4]) = u;
        }
        // W tile [n][k] (already tf32-rounded)
#pragma unroll
        for (int i = 0; i < 16; i++) {
            int e = t + 256 * i;
            int r = e >> 5, c4 = e & 31;
            float4 v = __ldg(reinterpret_cast<const float4*>(Wt + (size_t)r * DIM) + c4);
            *reinterpret_cast<float4*>(&Ws[r * SA + c4 * 4]) = v;
        }
        __syncthreads();

        // 16 k-steps of m16n8k8
#pragma unroll
        for (int ks = 0; ks < 16; ks++) {
            const int k0 = ks * 8;
            uint32_t a[4][4];
#pragma unroll
            for (int mi = 0; mi < 4; mi++) {
                const float* p = &As[(wm * 64 + mi * 16 + qid) * SA + k0 + qtl];
                a[mi][0] = __float_as_uint(p[0]);
                a[mi][1] = __float_as_uint(p[8 * SA]);
                a[mi][2] = __float_as_uint(p[4]);
                a[mi][3] = __float_as_uint(p[8 * SA + 4]);
            }
            uint32_t b[4][2];
#pragma unroll
            for (int ni = 0; ni < 4; ni++) {
                const float* p = &Ws[(wn * 32 + ni * 8 + qid) * SA + k0 + qtl];
                b[ni][0] = __float_as_uint(p[0]);
                b[ni][1] = __float_as_uint(p[4]);
            }
#pragma unroll
            for (int mi = 0; mi < 4; mi++)
#pragma unroll
                for (int ni = 0; ni < 4; ni++)
                    mma_tf32(acc[mi][ni], a[mi], b[ni]);
        }
    }

    // Epilogue: bias (+bias2), optional ReLU, float2 stores
#pragma unroll
    for (int ni = 0; ni < 4; ni++) {
        int col = wn * 32 + ni * 8 + qtl * 2;
        float bb0 = __ldg(b1 + col)     + (TWO ? __ldg(b2 + col)     : 0.0f);
        float bb1 = __ldg(b1 + col + 1) + (TWO ? __ldg(b2 + col + 1) : 0.0f);
#pragma unroll
        for (int mi = 0; mi < 4; mi++) {
            int r0 = row0 + wm * 64 + mi * 16 + qid;
            if (r0 < nrows) {
                float2 o;
                o.x = acc[mi][ni][0] + bb0;
                o.y = acc[mi][ni][1] + bb1;
                if (RELU) { o.x = fmaxf(o.x, 0.0f); o.y = fmaxf(o.y, 0.0f); }
                *reinterpret_cast<float2*>(out + (size_t)r0 * DIM + col) = o;
            }
            int r1 = r0 + 8;
            if (r1 < nrows) {
                float2 o;
                o.x = acc[mi][ni][2] + bb0;
                o.y = acc[mi][ni][3] + bb1;
                if (RELU) { o.x = fmaxf(o.x, 0.0f); o.y = fmaxf(o.y, 0.0f); }
                *reinterpret_cast<float2*>(out + (size_t)r1 * DIM + col) = o;
            }
        }
    }
}

// ---------------- host orchestration ----------------
static const size_t GEMM_SMEM = 2u * 128u * SA * sizeof(float);  // 135168 B

static void run_layer(const float* hd_in, const float* hp_in,
                      float* hd_out, float* hp_out,
                      const float* Wt /*3x[n][k]*/, const float* b, bool relu,
                      int* indptr, int* eidx,
                      float* agg1, float* agg2, float* aggp, float* rs) {
    const int gwb = (NN * 32 + 255) / 256;   // one warp per dst row
    gather_kernel<<<gwb, 256>>>(hd_in, indptr + 0 * (NN + 1), eidx + 0 * NEMAX,
                                rs + 0 * NN, rs + 1 * NN, agg1, NDRUG);
    gather_kernel<<<gwb, 256>>>(hp_in, indptr + 1 * (NN + 1), eidx + 1 * NEMAX,
                                rs + 2 * NN, rs + 3 * NN, agg2, NDRUG);
    gather_kernel<<<gwb, 256>>>(hp_in, indptr + 2 * (NN + 1), eidx + 2 * NEMAX,
                                rs + 4 * NN, rs + 5 * NN, aggp, NPROT);

    const int gblocks = (NDRUG + 127) / 128;
    if (relu) {
        gemm_mma<true, true><<<gblocks, 256, GEMM_SMEM>>>(
            agg1, agg2, Wt + 0 * DIM * DIM, Wt + 1 * DIM * DIM,
            b + 0 * DIM, b + 1 * DIM, hd_out, NDRUG);
        gemm_mma<true, false><<<gblocks, 256, GEMM_SMEM>>>(
            aggp, nullptr, Wt + 2 * DIM * DIM, nullptr,
            b + 2 * DIM, nullptr, hp_out, NPROT);
    } else {
        gemm_mma<false, true><<<gblocks, 256, GEMM_SMEM>>>(
            agg1, agg2, Wt + 0 * DIM * DIM, Wt + 1 * DIM * DIM,
            b + 0 * DIM, b + 1 * DIM, hd_out, NDRUG);
        gemm_mma<false, false><<<gblocks, 256, GEMM_SMEM>>>(
            aggp, nullptr, Wt + 2 * DIM * DIM, nullptr,
            b + 2 * DIM, nullptr, hp_out, NPROT);
    }
}

extern "C" void kernel_launch(void* const* d_in, const int* in_sizes, int n_in,
                              void* d_out, int out_size) {
    const float* hd0   = (const float*)d_in[0];
    const float* hp0   = (const float*)d_in[1];
    const int*   ddi_s = (const int*)d_in[2];
    const int*   ddi_d = (const int*)d_in[3];
    const int*   pdi_s = (const int*)d_in[4];
    const int*   pdi_d = (const int*)d_in[5];
    const int*   ppi_s = (const int*)d_in[6];
    const int*   ppi_d = (const int*)d_in[7];
    const float* W1 = (const float*)d_in[8];
    const float* b1 = (const float*)d_in[9];
    const float* W2 = (const float*)d_in[10];
    const float* b2 = (const float*)d_in[11];
    const float* W3 = (const float*)d_in[12];
    const float* b3 = (const float*)d_in[13];

    const int nE_ddi = in_sizes[2];
    const int nE_pdi = in_sizes[4];
    const int nE_ppi = in_sizes[6];

    cudaFuncSetAttribute(gemm_mma<true, true>,   cudaFuncAttributeMaxDynamicSharedMemorySize, (int)GEMM_SMEM);
    cudaFuncSetAttribute(gemm_mma<true, false>,  cudaFuncAttributeMaxDynamicSharedMemorySize, (int)GEMM_SMEM);
    cudaFuncSetAttribute(gemm_mma<false, true>,  cudaFuncAttributeMaxDynamicSharedMemorySize, (int)GEMM_SMEM);
    cudaFuncSetAttribute(gemm_mma<false, false>, cudaFuncAttributeMaxDynamicSharedMemorySize, (int)GEMM_SMEM);

    float *hd1, *hp1, *hd2, *hp2, *agg1, *agg2, *aggp, *rs, *wt;
    int *indptr, *cursor, *eidx, *bsum;
    cudaGetSymbolAddress((void**)&hd1, g_hd1);
    cudaGetSymbolAddress((void**)&hp1, g_hp1);
    cudaGetSymbolAddress((void**)&hd2, g_hd2);
    cudaGetSymbolAddress((void**)&hp2, g_hp2);
    cudaGetSymbolAddress((void**)&agg1, g_agg1);
    cudaGetSymbolAddress((void**)&agg2, g_agg2);
    cudaGetSymbolAddress((void**)&aggp, g_aggp);
    cudaGetSymbolAddress((void**)&rs, g_rs);
    cudaGetSymbolAddress((void**)&wt, g_Wt);
    cudaGetSymbolAddress((void**)&indptr, g_indptr);
    cudaGetSymbolAddress((void**)&cursor, g_cursor);
    cudaGetSymbolAddress((void**)&eidx, g_eidx);
    cudaGetSymbolAddress((void**)&bsum, g_bsum);

    // transposed+rounded weights (one launch for all 9 matrices)
    transpose_w9<<<(9 * DIM * DIM + 255) / 256, 256>>>(W1, W2, W3, wt);

    // degree histograms (float counts): one pass per relation
    cudaMemsetAsync(rs, 0, (size_t)6 * NN * sizeof(float), 0);
    count2_kernel<<<(nE_ddi + 255) / 256, 256>>>(ddi_s, ddi_d, rs + 0 * NN, rs + 1 * NN, nE_ddi);
    count2_kernel<<<(nE_pdi + 255) / 256, 256>>>(pdi_s, pdi_d, rs + 2 * NN, rs + 3 * NN, nE_pdi);
    count2_kernel<<<(nE_ppi + 255) / 256, 256>>>(ppi_s, ppi_d, rs + 4 * NN, rs + 5 * NN, nE_ppi);

    // CSR build, batched across the 3 relations
    const int nb = (NN + 1023) / 1024;     // 98
    const int tb = (NN + 255) / 256;       // 391
    scan1<<<dim3(nb, 3), 1024>>>(rs, indptr, bsum);
    scan2<<<3, 256>>>(bsum, nb);
    scan3<<<dim3(tb, 3), 256>>>(rs, indptr, bsum, cursor);   // also seeds cursor

    int nEmax = nE_ddi > nE_pdi ? nE_ddi : nE_pdi;
    if (nE_ppi > nEmax) nEmax = nE_ppi;
    fill3_kernel<<<dim3((nEmax + 255) / 256, 3), 256>>>(
        ddi_s, ddi_d, nE_ddi, pdi_s, pdi_d, nE_pdi, ppi_s, ppi_d, nE_ppi, cursor, eidx);

    // counts -> rsqrt(max(deg,1))  (after scans have consumed raw counts)
    rsqrt_kernel<<<(6 * NN + 255) / 256, 256>>>(rs, 6 * NN);

    float* outd = (float*)d_out;
    float* outp = outd + (size_t)NDRUG * DIM;

    run_layer(hd0, hp0, hd1, hp1, wt + 0 * 3 * DIM * DIM, b1, true,
              indptr, eidx, agg1, agg2, aggp, rs);
    run_layer(hd1, hp1, hd2, hp2, wt + 1 * 3 * DIM * DIM, b2, true,
              indptr, eidx, agg1, agg2, aggp, rs);
    run_layer(hd2, hp2, outd, outp, wt + 2 * 3 * DIM * DIM, b3, false,
              indptr, eidx, agg1, agg2, aggp, rs);
}

// round 7
// speedup vs baseline: 3.5644x; 1.1712x over previous
#include <cuda_runtime.h>
#include <cstdint>

#define NDRUG 100000
#define NPROT 100000
#define NN    100000
#define NEMAX 800000
#define DIM   128
#define KC    32        // k-chunk
#define SAK   36        // smem chunk row stride (floats); 36 mod 32 = 4 -> conflict-free quads
#define GBLK  782       // ceil(100000/128)

// ---------------- scratch ----------------
__device__ float g_hd1[(size_t)NDRUG * DIM];
__device__ float g_hp1[(size_t)NPROT * DIM];
__device__ float g_hd2[(size_t)NDRUG * DIM];
__device__ float g_hp2[(size_t)NPROT * DIM];
__device__ float g_agg1[(size_t)NDRUG * DIM];
__device__ float g_agg2[(size_t)NDRUG * DIM];
__device__ float g_aggp[(size_t)NPROT * DIM];
// [0]=ddi_out [1]=ddi_in [2]=pdi_out [3]=pdi_in [4]=ppi_out [5]=ppi_in
__device__ float g_rs[(size_t)6 * NN];
__device__ float g_Wt[(size_t)9 * DIM * DIM];  // transposed+tf32-rounded, [layer][rel][n][k]
__device__ int g_indptr[3 * (NN + 1)];
__device__ int g_cursor[3 * NN];
__device__ int g_eidx[3 * NEMAX];
__device__ int g_bsum[3 * 128];

// ---------------- helpers ----------------
__device__ __forceinline__ uint32_t sptr(const void* p) {
    return (uint32_t)__cvta_generic_to_shared(p);
}
__device__ __forceinline__ void cp_async16(uint32_t dst, const void* src, int sz) {
    asm volatile("cp.async.cg.shared.global [%0], [%1], 16, %2;" :: "r"(dst), "l"(src), "r"(sz));
}
__device__ __forceinline__ void mma_tf32(float c[4], const uint32_t a[4], const uint32_t b[2]) {
    asm volatile(
        "mma.sync.aligned.m16n8k8.row.col.f32.tf32.tf32.f32 "
        "{%0,%1,%2,%3}, {%4,%5,%6,%7}, {%8,%9}, {%0,%1,%2,%3};"
        : "+f"(c[0]), "+f"(c[1]), "+f"(c[2]), "+f"(c[3])
        : "r"(a[0]), "r"(a[1]), "r"(a[2]), "r"(a[3]), "r"(b[0]), "r"(b[1]));
}

// ---------------- preprocessing kernels ----------------
// batched degree count: grid.y = relation
__global__ void count2b(const int* __restrict__ s0, const int* __restrict__ d0, int n0,
                        const int* __restrict__ s1, const int* __restrict__ d1, int n1,
                        const int* __restrict__ s2, const int* __restrict__ d2, int n2,
                        float* __restrict__ rs) {
    const int rel = blockIdx.y;
    const int* src = rel == 0 ? s0 : (rel == 1 ? s1 : s2);
    const int* dst = rel == 0 ? d0 : (rel == 1 ? d1 : d2);
    int n = rel == 0 ? n0 : (rel == 1 ? n1 : n2);
    float* cs = rs + (size_t)(2 * rel) * NN;
    float* cd = rs + (size_t)(2 * rel + 1) * NN;
    int i = blockIdx.x * blockDim.x + threadIdx.x;
    if (i < n) {
        atomicAdd(&cs[src[i]], 1.0f);
        atomicAdd(&cd[dst[i]], 1.0f);
    }
}
__global__ void rsqrt_kernel(float* __restrict__ p, int n) {
    int i = blockIdx.x * blockDim.x + threadIdx.x;
    if (i < n) p[i] = rsqrtf(fmaxf(p[i], 1.0f));
}
__global__ void transpose_w9(const float* __restrict__ Wa, const float* __restrict__ Wb,
                             const float* __restrict__ Wc, float* __restrict__ Wt) {
    int i = blockIdx.x * blockDim.x + threadIdx.x;
    if (i < 9 * DIM * DIM) {
        int grp = i / (3 * DIM * DIM);
        int rem3 = i - grp * 3 * DIM * DIM;
        const float* W = grp == 0 ? Wa : (grp == 1 ? Wb : Wc);
        int rel = rem3 >> 14, rem = rem3 & 16383;
        int k = rem >> 7, n = rem & 127;
        float v = W[(rel << 14) + (k << 7) + n];
        uint32_t u;
        asm("cvt.rna.tf32.f32 %0, %1;" : "=r"(u) : "f"(v));
        Wt[i - rem + (n << 7) + k] = __uint_as_float(u);
    }
}

// ---------------- scans (batched over 3 relations) ----------------
__global__ void scan1(const float* __restrict__ rs, int* __restrict__ indptr,
                      int* __restrict__ bsum) {
    __shared__ int sm2[1024];
    const int rel = blockIdx.y;
    const float* cnt = rs + (size_t)(2 * rel + 1) * NN;
    int* excl = indptr + rel * (NN + 1);
    int tid = threadIdx.x;
    int i = blockIdx.x * 1024 + tid;
    int v = (i < NN) ? (int)cnt[i] : 0;
    sm2[tid] = v;
    __syncthreads();
#pragma unroll
    for (int off = 1; off < 1024; off <<= 1) {
        int t2 = (tid >= off) ? sm2[tid - off] : 0;
        __syncthreads();
        sm2[tid] += t2;
        __syncthreads();
    }
    if (i < NN) excl[i] = sm2[tid] - v;
    if (tid == 1023) bsum[rel * 128 + blockIdx.x] = sm2[1023];
}
__global__ void scan2(int* __restrict__ bsum, int nb) {
    __shared__ int sm2[256];
    const int rel = blockIdx.x;
    int tid = threadIdx.x;
    sm2[tid] = (tid < nb) ? bsum[rel * 128 + tid] : 0;
    __syncthreads();
#pragma unroll
    for (int off = 1; off < 256; off <<= 1) {
        int t2 = (tid >= off) ? sm2[tid - off] : 0;
        __syncthreads();
        sm2[tid] += t2;
        __syncthreads();
    }
    if (tid < nb) bsum[rel * 128 + tid] = sm2[tid];
}
__global__ void scan3(const float* __restrict__ rs, int* __restrict__ indptr,
                      const int* __restrict__ bsum, int* __restrict__ cursor) {
    const int rel = blockIdx.y;
    const float* cnt = rs + (size_t)(2 * rel + 1) * NN;
    int* excl = indptr + rel * (NN + 1);
    int i = blockIdx.x * blockDim.x + threadIdx.x;
    if (i < NN) {
        int b = i >> 10;
        int off = b ? bsum[rel * 128 + b - 1] : 0;
        int e = excl[i] + off;
        excl[i] = e;
        cursor[rel * NN + i] = e;
        if (i == NN - 1) excl[NN] = e + (int)cnt[i];
    }
}
__global__ void fill3_kernel(const int* __restrict__ s0, const int* __restrict__ d0, int n0,
                             const int* __restrict__ s1, const int* __restrict__ d1, int n1,
                             const int* __restrict__ s2, const int* __restrict__ d2, int n2,
                             int* __restrict__ cursor, int* __restrict__ eidx) {
    const int rel = blockIdx.y;
    const int* src = rel == 0 ? s0 : (rel == 1 ? s1 : s2);
    const int* dst = rel == 0 ? d0 : (rel == 1 ? d1 : d2);
    int nE = rel == 0 ? n0 : (rel == 1 ? n1 : n2);
    int e = blockIdx.x * blockDim.x + threadIdx.x;
    if (e < nE) {
        int p = atomicAdd(&cursor[rel * NN + dst[e]], 1);
        eidx[(size_t)rel * NEMAX + p] = src[e];
    }
}

// ---------------- batched CSR gather (grid.y = relation), tf32-rounded output ----------------
__global__ void __launch_bounds__(256)
gather3(const float* __restrict__ hd, const float* __restrict__ hp,
        const int* __restrict__ indptr, const int* __restrict__ eidx,
        const float* __restrict__ rs,
        float* __restrict__ agg1, float* __restrict__ agg2, float* __restrict__ aggp) {
    const int rel = blockIdx.y;
    const float* h   = (rel == 0) ? hd : hp;
    const int*   ip  = indptr + rel * (NN + 1);
    const int*   ei  = eidx + (size_t)rel * NEMAX;
    const float* rso = rs + (size_t)(2 * rel) * NN;
    const float* rsi = rs + (size_t)(2 * rel + 1) * NN;
    float* agg = (rel == 0) ? agg1 : ((rel == 1) ? agg2 : aggp);

    int w = (blockIdx.x * blockDim.x + threadIdx.x) >> 5;
    int lane = threadIdx.x & 31;
    if (w >= NN) return;
    int s0 = __ldg(ip + w), s1 = __ldg(ip + w + 1);
    float4 acc = make_float4(0.f, 0.f, 0.f, 0.f);
    for (int base = s0; base < s1; base += 32) {
        int m = min(32, s1 - base);
        int se = (lane < m) ? __ldg(ei + base + lane) : 0;
#pragma unroll 4
        for (int i = 0; i < m; i++) {
            int s = __shfl_sync(0xFFFFFFFFu, se, i);
            float sc = __ldg(rso + s);
            float4 v = __ldg(reinterpret_cast<const float4*>(h + (size_t)s * DIM) + lane);
            acc.x += sc * v.x; acc.y += sc * v.y; acc.z += sc * v.z; acc.w += sc * v.w;
        }
    }
    float ri = __ldg(rsi + w);
    acc.x *= ri; acc.y *= ri; acc.z *= ri; acc.w *= ri;
    // round to tf32 here so the GEMM can cp.async raw bytes
    uint4 u;
    asm("cvt.rna.tf32.f32 %0, %1;" : "=r"(u.x) : "f"(acc.x));
    asm("cvt.rna.tf32.f32 %0, %1;" : "=r"(u.y) : "f"(acc.y));
    asm("cvt.rna.tf32.f32 %0, %1;" : "=r"(u.z) : "f"(acc.z));
    asm("cvt.rna.tf32.f32 %0, %1;" : "=r"(u.w) : "f"(acc.w));
    reinterpret_cast<uint4*>(agg + (size_t)w * DIM)[lane] = u;
}

// ---------------- cp.async double-buffered tf32 GEMM body ----------------
template<bool RELU, bool TWO>
__device__ __forceinline__ void gemm_body(
    int bx, const float* __restrict__ A1, const float* __restrict__ A2,
    const float* __restrict__ Wt1, const float* __restrict__ Wt2,
    const float* __restrict__ b1, const float* __restrict__ b2,
    float* __restrict__ out, int nrows, float* sm) {
    float* As = sm;                      // [2][128][SAK]
    float* Ws = sm + 2 * 128 * SAK;      // [2][128][SAK]

    const int t = threadIdx.x;
    const int lane = t & 31, wid = t >> 5;
    const int wm = wid >> 2, wn = wid & 3;
    const int row0 = bx * 128;
    const int qid = lane >> 2, qtl = lane & 3;

    float acc[4][4][4];
#pragma unroll
    for (int mi = 0; mi < 4; mi++)
#pragma unroll
        for (int ni = 0; ni < 4; ni++)
#pragma unroll
            for (int j = 0; j < 4; j++) acc[mi][ni][j] = 0.0f;

    const int C = TWO ? 8 : 4;

    auto issue = [&](int c) {
        int sidx = TWO ? (c >> 2) : 0;
        int kc   = TWO ? (c & 3) : c;
        const float* A = sidx ? A2 : A1;
        const float* W = sidx ? Wt2 : Wt1;
        int stage = c & 1;
        float* as = As + stage * 128 * SAK;
        float* ws = Ws + stage * 128 * SAK;
#pragma unroll
        for (int i = 0; i < 4; i++) {
            int idx = t + 256 * i;
            int r = idx >> 3, c4 = idx & 7;      // 8 float4 per 32-float row chunk
            int row = row0 + r;
            int sz = (row < nrows) ? 16 : 0;     // zero-fill OOB rows
            cp_async16(sptr(as + r * SAK + c4 * 4), A + (size_t)row * DIM + kc * KC + c4 * 4, sz);
            cp_async16(sptr(ws + r * SAK + c4 * 4), W + (size_t)r * DIM + kc * KC + c4 * 4, 16);
        }
        asm volatile("cp.async.commit_group;" ::: "memory");
    };

    issue(0);
    issue(1);
    for (int c = 0; c < C; c++) {
        if (c == C - 1) asm volatile("cp.async.wait_group 0;" ::: "memory");
        else            asm volatile("cp.async.wait_group 1;" ::: "memory");
        __syncthreads();
        const int stage = c & 1;
        const float* as = As + stage * 128 * SAK;
        const float* ws = Ws + stage * 128 * SAK;
#pragma unroll
        for (int ks = 0; ks < 4; ks++) {
            const int k0 = ks * 8;
            uint32_t a[4][4], bf[4][2];
#pragma unroll
            for (int mi = 0; mi < 4; mi++) {
                const float* p = &as[(wm * 64 + mi * 16 + qid) * SAK + k0 + qtl];
                a[mi][0] = __float_as_uint(p[0]);
                a[mi][1] = __float_as_uint(p[8 * SAK]);
                a[mi][2] = __float_as_uint(p[4]);
                a[mi][3] = __float_as_uint(p[8 * SAK + 4]);
            }
#pragma unroll
            for (int ni = 0; ni < 4; ni++) {
                const float* p = &ws[(wn * 32 + ni * 8 + qid) * SAK + k0 + qtl];
                bf[ni][0] = __float_as_uint(p[0]);
                bf[ni][1] = __float_as_uint(p[4]);
            }
#pragma unroll
            for (int mi = 0; mi < 4; mi++)
#pragma unroll
                for (int ni = 0; ni < 4; ni++)
                    mma_tf32(acc[mi][ni], a[mi], bf[ni]);
        }
        __syncthreads();
        if (c + 2 < C) issue(c + 2);
    }

    // Epilogue
#pragma unroll
    for (int ni = 0; ni < 4; ni++) {
        int col = wn * 32 + ni * 8 + qtl * 2;
        float bb0 = __ldg(b1 + col)     + (TWO ? __ldg(b2 + col)     : 0.0f);
        float bb1 = __ldg(b1 + col + 1) + (TWO ? __ldg(b2 + col + 1) : 0.0f);
#pragma unroll
        for (int mi = 0; mi < 4; mi++) {
            int r0 = row0 + wm * 64 + mi * 16 + qid;
            if (r0 < nrows) {
                float2 o;
                o.x = acc[mi][ni][0] + bb0;
                o.y = acc[mi][ni][1] + bb1;
                if (RELU) { o.x = fmaxf(o.x, 0.0f); o.y = fmaxf(o.y, 0.0f); }
                *reinterpret_cast<float2*>(out + (size_t)r0 * DIM + col) = o;
            }
            int r1 = r0 + 8;
            if (r1 < nrows) {
                float2 o;
                o.x = acc[mi][ni][2] + bb0;
                o.y = acc[mi][ni][3] + bb1;
                if (RELU) { o.x = fmaxf(o.x, 0.0f); o.y = fmaxf(o.y, 0.0f); }
                *reinterpret_cast<float2*>(out + (size_t)r1 * DIM + col) = o;
            }
        }
    }
}

// One launch per layer: blocks [0,split) = drug (DDI+PDI dual-source), rest = protein (PPI)
template<bool RELU>
__global__ void __launch_bounds__(256)
layer_mma(const float* __restrict__ agg1, const float* __restrict__ agg2,
          const float* __restrict__ aggp, const float* __restrict__ Wt,
          const float* __restrict__ bb, float* __restrict__ outd,
          float* __restrict__ outp, int split) {
    extern __shared__ float sm[];
    if ((int)blockIdx.x < split)
        gemm_body<RELU, true>(blockIdx.x, agg1, agg2,
                              Wt, Wt + DIM * DIM, bb, bb + DIM, outd, NDRUG, sm);
    else
        gemm_body<RELU, false>(blockIdx.x - split, aggp, nullptr,
                               Wt + 2 * DIM * DIM, nullptr, bb + 2 * DIM, nullptr, outp, NPROT, sm);
}

// ---------------- host orchestration ----------------
static const size_t GEMM_SMEM = 4u * 128u * SAK * sizeof(float);  // 73728 B

static void run_layer(const float* hd_in, const float* hp_in,
                      float* hd_out, float* hp_out,
                      const float* Wt, const float* b, bool relu,
                      int* indptr, int* eidx,
                      float* agg1, float* agg2, float* aggp, float* rs) {
    gather3<<<dim3((NN * 32 + 255) / 256, 3), 256>>>(hd_in, hp_in, indptr, eidx, rs,
                                                     agg1, agg2, aggp);
    if (relu)
        layer_mma<true><<<2 * GBLK, 256, GEMM_SMEM>>>(agg1, agg2, aggp, Wt, b,
                                                      hd_out, hp_out, GBLK);
    else
        layer_mma<false><<<2 * GBLK, 256, GEMM_SMEM>>>(agg1, agg2, aggp, Wt, b,
                                                       hd_out, hp_out, GBLK);
}

extern "C" void kernel_launch(void* const* d_in, const int* in_sizes, int n_in,
                              void* d_out, int out_size) {
    const float* hd0   = (const float*)d_in[0];
    const float* hp0   = (const float*)d_in[1];
    const int*   ddi_s = (const int*)d_in[2];
    const int*   ddi_d = (const int*)d_in[3];
    const int*   pdi_s = (const int*)d_in[4];
    const int*   pdi_d = (const int*)d_in[5];
    const int*   ppi_s = (const int*)d_in[6];
    const int*   ppi_d = (const int*)d_in[7];
    const float* W1 = (const float*)d_in[8];
    const float* b1 = (const float*)d_in[9];
    const float* W2 = (const float*)d_in[10];
    const float* b2 = (const float*)d_in[11];
    const float* W3 = (const float*)d_in[12];
    const float* b3 = (const float*)d_in[13];

    const int nE_ddi = in_sizes[2];
    const int nE_pdi = in_sizes[4];
    const int nE_ppi = in_sizes[6];

    cudaFuncSetAttribute(layer_mma<true>,  cudaFuncAttributeMaxDynamicSharedMemorySize, (int)GEMM_SMEM);
    cudaFuncSetAttribute(layer_mma<false>, cudaFuncAttributeMaxDynamicSharedMemorySize, (int)GEMM_SMEM);

    float *hd1, *hp1, *hd2, *hp2, *agg1, *agg2, *aggp, *rs, *wt;
    int *indptr, *cursor, *eidx, *bsum;
    cudaGetSymbolAddress((void**)&hd1, g_hd1);
    cudaGetSymbolAddress((void**)&hp1, g_hp1);
    cudaGetSymbolAddress((void**)&hd2, g_hd2);
    cudaGetSymbolAddress((void**)&hp2, g_hp2);
    cudaGetSymbolAddress((void**)&agg1, g_agg1);
    cudaGetSymbolAddress((void**)&agg2, g_agg2);
    cudaGetSymbolAddress((void**)&aggp, g_aggp);
    cudaGetSymbolAddress((void**)&rs, g_rs);
    cudaGetSymbolAddress((void**)&wt, g_Wt);
    cudaGetSymbolAddress((void**)&indptr, g_indptr);
    cudaGetSymbolAddress((void**)&cursor, g_cursor);
    cudaGetSymbolAddress((void**)&eidx, g_eidx);
    cudaGetSymbolAddress((void**)&bsum, g_bsum);

    transpose_w9<<<(9 * DIM * DIM + 255) / 256, 256>>>(W1, W2, W3, wt);

    cudaMemsetAsync(rs, 0, (size_t)6 * NN * sizeof(float), 0);
    int nEmax = nE_ddi > nE_pdi ? nE_ddi : nE_pdi;
    if (nE_ppi > nEmax) nEmax = nE_ppi;
    count2b<<<dim3((nEmax + 255) / 256, 3), 256>>>(
        ddi_s, ddi_d, nE_ddi, pdi_s, pdi_d, nE_pdi, ppi_s, ppi_d, nE_ppi, rs);

    const int nb = (NN + 1023) / 1024;   // 98
    const int tb = (NN + 255) / 256;
    scan1<<<dim3(nb, 3), 1024>>>(rs, indptr, bsum);
    scan2<<<3, 256>>>(bsum, nb);
    scan3<<<dim3(tb, 3), 256>>>(rs, indptr, bsum, cursor);

    fill3_kernel<<<dim3((nEmax + 255) / 256, 3), 256>>>(
        ddi_s, ddi_d, nE_ddi, pdi_s, pdi_d, nE_pdi, ppi_s, ppi_d, nE_ppi, cursor, eidx);

    rsqrt_kernel<<<(6 * NN + 255) / 256, 256>>>(rs, 6 * NN);

    float* outd = (float*)d_out;
    float* outp = outd + (size_t)NDRUG * DIM;

    run_layer(hd0, hp0, hd1, hp1, wt + 0 * 3 * DIM * DIM, b1, true,
              indptr, eidx, agg1, agg2, aggp, rs);
    run_layer(hd1, hp1, hd2, hp2, wt + 1 * 3 * DIM * DIM, b2, true,
              indptr, eidx, agg1, agg2, aggp, rs);
    run_layer(hd2, hp2, outd, outp, wt + 2 * 3 * DIM * DIM, b3, false,
              indptr, eidx, agg1, agg2, aggp, rs);
}

// round 8
// speedup vs baseline: 3.7374x; 1.0485x over previous
#include <cuda_runtime.h>
#include <cuda_bf16.h>
#include <cstdint>

#define NDRUG 100000
#define NPROT 100000
#define NN    100000
#define NEMAX 800000
#define DIM   128
#define KC    32        // k-chunk
#define SAK   36        // smem chunk row stride (floats)
#define GBLK  782       // ceil(100000/128)

// ---------------- scratch ----------------
// bf16 feature buffers (ping-pong): A = inputs / layer2 out, B = layer1 out
__device__ __nv_bfloat16 g_bfA_d[(size_t)NN * DIM];
__device__ __nv_bfloat16 g_bfA_p[(size_t)NN * DIM];
__device__ __nv_bfloat16 g_bfB_d[(size_t)NN * DIM];
__device__ __nv_bfloat16 g_bfB_p[(size_t)NN * DIM];
__device__ float g_agg1[(size_t)NDRUG * DIM];
__device__ float g_agg2[(size_t)NDRUG * DIM];
__device__ float g_aggp[(size_t)NPROT * DIM];
// [0]=ddi_out [1]=ddi_in [2]=pdi_out [3]=pdi_in [4]=ppi_out [5]=ppi_in
__device__ float g_rs[(size_t)6 * NN];
__device__ float g_Wt[(size_t)9 * DIM * DIM];
__device__ int g_indptr[3 * (NN + 1)];
__device__ int g_cursor[3 * NN];
__device__ int g_eidx[3 * NEMAX];
__device__ int g_bsum[3 * 128];

// ---------------- helpers ----------------
__device__ __forceinline__ uint32_t sptr(const void* p) {
    return (uint32_t)__cvta_generic_to_shared(p);
}
__device__ __forceinline__ void cp_async16(uint32_t dst, const void* src, int sz) {
    asm volatile("cp.async.cg.shared.global [%0], [%1], 16, %2;" :: "r"(dst), "l"(src), "r"(sz));
}
__device__ __forceinline__ void mma_tf32(float c[4], const uint32_t a[4], const uint32_t b[2]) {
    asm volatile(
        "mma.sync.aligned.m16n8k8.row.col.f32.tf32.tf32.f32 "
        "{%0,%1,%2,%3}, {%4,%5,%6,%7}, {%8,%9}, {%0,%1,%2,%3};"
        : "+f"(c[0]), "+f"(c[1]), "+f"(c[2]), "+f"(c[3])
        : "r"(a[0]), "r"(a[1]), "r"(a[2]), "r"(a[3]), "r"(b[0]), "r"(b[1]));
}

// ---------------- preprocessing kernels ----------------
__global__ void count2b(const int* __restrict__ s0, const int* __restrict__ d0, int n0,
                        const int* __restrict__ s1, const int* __restrict__ d1, int n1,
                        const int* __restrict__ s2, const int* __restrict__ d2, int n2,
                        float* __restrict__ rs) {
    const int rel = blockIdx.y;
    const int* src = rel == 0 ? s0 : (rel == 1 ? s1 : s2);
    const int* dst = rel == 0 ? d0 : (rel == 1 ? d1 : d2);
    int n = rel == 0 ? n0 : (rel == 1 ? n1 : n2);
    float* cs = rs + (size_t)(2 * rel) * NN;
    float* cd = rs + (size_t)(2 * rel + 1) * NN;
    int i = blockIdx.x * blockDim.x + threadIdx.x;
    if (i < n) {
        atomicAdd(&cs[src[i]], 1.0f);
        atomicAdd(&cd[dst[i]], 1.0f);
    }
}
__global__ void rsqrt_kernel(float* __restrict__ p, int n) {
    int i = blockIdx.x * blockDim.x + threadIdx.x;
    if (i < n) p[i] = rsqrtf(fmaxf(p[i], 1.0f));
}
__global__ void transpose_w9(const float* __restrict__ Wa, const float* __restrict__ Wb,
                             const float* __restrict__ Wc, float* __restrict__ Wt) {
    int i = blockIdx.x * blockDim.x + threadIdx.x;
    if (i < 9 * DIM * DIM) {
        int grp = i / (3 * DIM * DIM);
        int rem3 = i - grp * 3 * DIM * DIM;
        const float* W = grp == 0 ? Wa : (grp == 1 ? Wb : Wc);
        int rel = rem3 >> 14, rem = rem3 & 16383;
        int k = rem >> 7, n = rem & 127;
        float v = W[(rel << 14) + (k << 7) + n];
        uint32_t u;
        asm("cvt.rna.tf32.f32 %0, %1;" : "=r"(u) : "f"(v));
        Wt[i - rem + (n << 7) + k] = __uint_as_float(u);
    }
}
// convert input fp32 features to bf16 (both node types, one launch)
__global__ void to_bf16(const float* __restrict__ a, const float* __restrict__ b,
                        __nv_bfloat16* __restrict__ oa, __nv_bfloat16* __restrict__ ob) {
    const int n4 = NN * DIM / 4;
    int i = blockIdx.x * blockDim.x + threadIdx.x;
    if (i < n4) {
        float4 v = __ldg(reinterpret_cast<const float4*>(a) + i);
        reinterpret_cast<__nv_bfloat162*>(oa)[2 * i]     = __floats2bfloat162_rn(v.x, v.y);
        reinterpret_cast<__nv_bfloat162*>(oa)[2 * i + 1] = __floats2bfloat162_rn(v.z, v.w);
    } else if (i < 2 * n4) {
        int j = i - n4;
        float4 v = __ldg(reinterpret_cast<const float4*>(b) + j);
        reinterpret_cast<__nv_bfloat162*>(ob)[2 * j]     = __floats2bfloat162_rn(v.x, v.y);
        reinterpret_cast<__nv_bfloat162*>(ob)[2 * j + 1] = __floats2bfloat162_rn(v.z, v.w);
    }
}

// ---------------- scans (batched over 3 relations) ----------------
__global__ void scan1(const float* __restrict__ rs, int* __restrict__ indptr,
                      int* __restrict__ bsum) {
    __shared__ int sm2[1024];
    const int rel = blockIdx.y;
    const float* cnt = rs + (size_t)(2 * rel + 1) * NN;
    int* excl = indptr + rel * (NN + 1);
    int tid = threadIdx.x;
    int i = blockIdx.x * 1024 + tid;
    int v = (i < NN) ? (int)cnt[i] : 0;
    sm2[tid] = v;
    __syncthreads();
#pragma unroll
    for (int off = 1; off < 1024; off <<= 1) {
        int t2 = (tid >= off) ? sm2[tid - off] : 0;
        __syncthreads();
        sm2[tid] += t2;
        __syncthreads();
    }
    if (i < NN) excl[i] = sm2[tid] - v;
    if (tid == 1023) bsum[rel * 128 + blockIdx.x] = sm2[1023];
}
__global__ void scan2(int* __restrict__ bsum, int nb) {
    __shared__ int sm2[256];
    const int rel = blockIdx.x;
    int tid = threadIdx.x;
    sm2[tid] = (tid < nb) ? bsum[rel * 128 + tid] : 0;
    __syncthreads();
#pragma unroll
    for (int off = 1; off < 256; off <<= 1) {
        int t2 = (tid >= off) ? sm2[tid - off] : 0;
        __syncthreads();
        sm2[tid] += t2;
        __syncthreads();
    }
    if (tid < nb) bsum[rel * 128 + tid] = sm2[tid];
}
__global__ void scan3(const float* __restrict__ rs, int* __restrict__ indptr,
                      const int* __restrict__ bsum, int* __restrict__ cursor) {
    const int rel = blockIdx.y;
    const float* cnt = rs + (size_t)(2 * rel + 1) * NN;
    int* excl = indptr + rel * (NN + 1);
    int i = blockIdx.x * blockDim.x + threadIdx.x;
    if (i < NN) {
        int b = i >> 10;
        int off = b ? bsum[rel * 128 + b - 1] : 0;
        int e = excl[i] + off;
        excl[i] = e;
        cursor[rel * NN + i] = e;
        if (i == NN - 1) excl[NN] = e + (int)cnt[i];
    }
}
__global__ void fill3_kernel(const int* __restrict__ s0, const int* __restrict__ d0, int n0,
                             const int* __restrict__ s1, const int* __restrict__ d1, int n1,
                             const int* __restrict__ s2, const int* __restrict__ d2, int n2,
                             int* __restrict__ cursor, int* __restrict__ eidx) {
    const int rel = blockIdx.y;
    const int* src = rel == 0 ? s0 : (rel == 1 ? s1 : s2);
    const int* dst = rel == 0 ? d0 : (rel == 1 ? d1 : d2);
    int nE = rel == 0 ? n0 : (rel == 1 ? n1 : n2);
    int e = blockIdx.x * blockDim.x + threadIdx.x;
    if (e < nE) {
        int p = atomicAdd(&cursor[rel * NN + dst[e]], 1);
        eidx[(size_t)rel * NEMAX + p] = src[e];
    }
}

// ---------------- batched CSR gather over bf16 features (grid.y = relation) ----------------
__global__ void __launch_bounds__(256)
gather3(const __nv_bfloat16* __restrict__ hd, const __nv_bfloat16* __restrict__ hp,
        const int* __restrict__ indptr, const int* __restrict__ eidx,
        const float* __restrict__ rs,
        float* __restrict__ agg1, float* __restrict__ agg2, float* __restrict__ aggp) {
    const int rel = blockIdx.y;
    const __nv_bfloat16* h = (rel == 0) ? hd : hp;
    const int*   ip  = indptr + rel * (NN + 1);
    const int*   ei  = eidx + (size_t)rel * NEMAX;
    const float* rso = rs + (size_t)(2 * rel) * NN;
    const float* rsi = rs + (size_t)(2 * rel + 1) * NN;
    float* agg = (rel == 0) ? agg1 : ((rel == 1) ? agg2 : aggp);

    int w = (blockIdx.x * blockDim.x + threadIdx.x) >> 5;
    int lane = threadIdx.x & 31;
    if (w >= NN) return;
    int s0 = __ldg(ip + w), s1 = __ldg(ip + w + 1);
    float4 acc = make_float4(0.f, 0.f, 0.f, 0.f);
    for (int base = s0; base < s1; base += 32) {
        int m = min(32, s1 - base);
        int se = (lane < m) ? __ldg(ei + base + lane) : 0;
#pragma unroll 4
        for (int i = 0; i < m; i++) {
            int s = __shfl_sync(0xFFFFFFFFu, se, i);
            float sc = __ldg(rso + s);
            uint2 raw = __ldg(reinterpret_cast<const uint2*>(h + (size_t)s * DIM) + lane);
            __nv_bfloat162 b0 = *reinterpret_cast<__nv_bfloat162*>(&raw.x);
            __nv_bfloat162 b1 = *reinterpret_cast<__nv_bfloat162*>(&raw.y);
            float2 f0 = __bfloat1622float2(b0);
            float2 f1 = __bfloat1622float2(b1);
            acc.x += sc * f0.x; acc.y += sc * f0.y;
            acc.z += sc * f1.x; acc.w += sc * f1.y;
        }
    }
    float ri = __ldg(rsi + w);
    acc.x *= ri; acc.y *= ri; acc.z *= ri; acc.w *= ri;
    // round to tf32 so the GEMM can cp.async raw bytes
    uint4 u;
    asm("cvt.rna.tf32.f32 %0, %1;" : "=r"(u.x) : "f"(acc.x));
    asm("cvt.rna.tf32.f32 %0, %1;" : "=r"(u.y) : "f"(acc.y));
    asm("cvt.rna.tf32.f32 %0, %1;" : "=r"(u.z) : "f"(acc.z));
    asm("cvt.rna.tf32.f32 %0, %1;" : "=r"(u.w) : "f"(acc.w));
    reinterpret_cast<uint4*>(agg + (size_t)w * DIM)[lane] = u;
}

// ---------------- cp.async double-buffered tf32 GEMM body ----------------
// BF16OUT: write __nv_bfloat16 (intermediate layers); else fp32 (final layer)
template<bool RELU, bool TWO, bool BF16OUT>
__device__ __forceinline__ void gemm_body(
    int bx, const float* __restrict__ A1, const float* __restrict__ A2,
    const float* __restrict__ Wt1, const float* __restrict__ Wt2,
    const float* __restrict__ b1, const float* __restrict__ b2,
    void* __restrict__ out, int nrows, float* sm) {
    float* As = sm;                      // [2][128][SAK]
    float* Ws = sm + 2 * 128 * SAK;      // [2][128][SAK]

    const int t = threadIdx.x;
    const int lane = t & 31, wid = t >> 5;
    const int wm = wid >> 2, wn = wid & 3;
    const int row0 = bx * 128;
    const int qid = lane >> 2, qtl = lane & 3;

    float acc[4][4][4];
#pragma unroll
    for (int mi = 0; mi < 4; mi++)
#pragma unroll
        for (int ni = 0; ni < 4; ni++)
#pragma unroll
            for (int j = 0; j < 4; j++) acc[mi][ni][j] = 0.0f;

    const int C = TWO ? 8 : 4;

    auto issue = [&](int c) {
        int sidx = TWO ? (c >> 2) : 0;
        int kc   = TWO ? (c & 3) : c;
        const float* A = sidx ? A2 : A1;
        const float* W = sidx ? Wt2 : Wt1;
        int stage = c & 1;
        float* as = As + stage * 128 * SAK;
        float* ws = Ws + stage * 128 * SAK;
#pragma unroll
        for (int i = 0; i < 4; i++) {
            int idx = t + 256 * i;
            int r = idx >> 3, c4 = idx & 7;
            int row = row0 + r;
            int sz = (row < nrows) ? 16 : 0;
            cp_async16(sptr(as + r * SAK + c4 * 4), A + (size_t)row * DIM + kc * KC + c4 * 4, sz);
            cp_async16(sptr(ws + r * SAK + c4 * 4), W + (size_t)r * DIM + kc * KC + c4 * 4, 16);
        }
        asm volatile("cp.async.commit_group;" ::: "memory");
    };

    issue(0);
    issue(1);
    for (int c = 0; c < C; c++) {
        if (c == C - 1) asm volatile("cp.async.wait_group 0;" ::: "memory");
        else            asm volatile("cp.async.wait_group 1;" ::: "memory");
        __syncthreads();
        const int stage = c & 1;
        const float* as = As + stage * 128 * SAK;
        const float* ws = Ws + stage * 128 * SAK;
#pragma unroll
        for (int ks = 0; ks < 4; ks++) {
            const int k0 = ks * 8;
            uint32_t a[4][4], bf[4][2];
#pragma unroll
            for (int mi = 0; mi < 4; mi++) {
                const float* p = &as[(wm * 64 + mi * 16 + qid) * SAK + k0 + qtl];
                a[mi][0] = __float_as_uint(p[0]);
                a[mi][1] = __float_as_uint(p[8 * SAK]);
                a[mi][2] = __float_as_uint(p[4]);
                a[mi][3] = __float_as_uint(p[8 * SAK + 4]);
            }
#pragma unroll
            for (int ni = 0; ni < 4; ni++) {
                const float* p = &ws[(wn * 32 + ni * 8 + qid) * SAK + k0 + qtl];
                bf[ni][0] = __float_as_uint(p[0]);
                bf[ni][1] = __float_as_uint(p[4]);
            }
#pragma unroll
            for (int mi = 0; mi < 4; mi++)
#pragma unroll
                for (int ni = 0; ni < 4; ni++)
                    mma_tf32(acc[mi][ni], a[mi], bf[ni]);
        }
        __syncthreads();
        if (c + 2 < C) issue(c + 2);
    }

    // Epilogue
#pragma unroll
    for (int ni = 0; ni < 4; ni++) {
        int col = wn * 32 + ni * 8 + qtl * 2;
        float bb0 = __ldg(b1 + col)     + (TWO ? __ldg(b2 + col)     : 0.0f);
        float bb1 = __ldg(b1 + col + 1) + (TWO ? __ldg(b2 + col + 1) : 0.0f);
#pragma unroll
        for (int mi = 0; mi < 4; mi++) {
#pragma unroll
            for (int half = 0; half < 2; half++) {
                int r = row0 + wm * 64 + mi * 16 + qid + half * 8;
                if (r < nrows) {
                    float ox = acc[mi][ni][half * 2 + 0] + bb0;
                    float oy = acc[mi][ni][half * 2 + 1] + bb1;
                    if (RELU) { ox = fmaxf(ox, 0.0f); oy = fmaxf(oy, 0.0f); }
                    if (BF16OUT) {
                        *reinterpret_cast<__nv_bfloat162*>(
                            (__nv_bfloat16*)out + (size_t)r * DIM + col) =
                            __floats2bfloat162_rn(ox, oy);
                    } else {
                        float2 o; o.x = ox; o.y = oy;
                        *reinterpret_cast<float2*>((float*)out + (size_t)r * DIM + col) = o;
                    }
                }
            }
        }
    }
}

template<bool RELU, bool BF16OUT>
__global__ void __launch_bounds__(256)
layer_mma(const float* __restrict__ agg1, const float* __restrict__ agg2,
          const float* __restrict__ aggp, const float* __restrict__ Wt,
          const float* __restrict__ bb, void* __restrict__ outd,
          void* __restrict__ outp, int split) {
    extern __shared__ float sm[];
    if ((int)blockIdx.x < split)
        gemm_body<RELU, true, BF16OUT>(blockIdx.x, agg1, agg2,
                                       Wt, Wt + DIM * DIM, bb, bb + DIM, outd, NDRUG, sm);
    else
        gemm_body<RELU, false, BF16OUT>(blockIdx.x - split, aggp, nullptr,
                                        Wt + 2 * DIM * DIM, nullptr, bb + 2 * DIM, nullptr,
                                        outp, NPROT, sm);
}

// ---------------- host orchestration ----------------
static const size_t GEMM_SMEM = 4u * 128u * SAK * sizeof(float);  // 73728 B

template<bool RELU, bool BF16OUT>
static void launch_layer(const __nv_bfloat16* hd_in, const __nv_bfloat16* hp_in,
                         void* hd_out, void* hp_out,
                         const float* Wt, const float* b,
                         int* indptr, int* eidx,
                         float* agg1, float* agg2, float* aggp, float* rs) {
    gather3<<<dim3((NN * 32 + 255) / 256, 3), 256>>>(hd_in, hp_in, indptr, eidx, rs,
                                                     agg1, agg2, aggp);
    layer_mma<RELU, BF16OUT><<<2 * GBLK, 256, GEMM_SMEM>>>(agg1, agg2, aggp, Wt, b,
                                                           hd_out, hp_out, GBLK);
}

extern "C" void kernel_launch(void* const* d_in, const int* in_sizes, int n_in,
                              void* d_out, int out_size) {
    const float* hd0   = (const float*)d_in[0];
    const float* hp0   = (const float*)d_in[1];
    const int*   ddi_s = (const int*)d_in[2];
    const int*   ddi_d = (const int*)d_in[3];
    const int*   pdi_s = (const int*)d_in[4];
    const int*   pdi_d = (const int*)d_in[5];
    const int*   ppi_s = (const int*)d_in[6];
    const int*   ppi_d = (const int*)d_in[7];
    const float* W1 = (const float*)d_in[8];
    const float* b1 = (const float*)d_in[9];
    const float* W2 = (const float*)d_in[10];
    const float* b2 = (const float*)d_in[11];
    const float* W3 = (const float*)d_in[12];
    const float* b3 = (const float*)d_in[13];

    const int nE_ddi = in_sizes[2];
    const int nE_pdi = in_sizes[4];
    const int nE_ppi = in_sizes[6];

    cudaFuncSetAttribute(layer_mma<true, true>,   cudaFuncAttributeMaxDynamicSharedMemorySize, (int)GEMM_SMEM);
    cudaFuncSetAttribute(layer_mma<false, false>, cudaFuncAttributeMaxDynamicSharedMemorySize, (int)GEMM_SMEM);

    float *agg1, *agg2, *aggp, *rs, *wt;
    __nv_bfloat16 *bfA_d, *bfA_p, *bfB_d, *bfB_p;
    int *indptr, *cursor, *eidx, *bsum;
    cudaGetSymbolAddress((void**)&bfA_d, g_bfA_d);
    cudaGetSymbolAddress((void**)&bfA_p, g_bfA_p);
    cudaGetSymbolAddress((void**)&bfB_d, g_bfB_d);
    cudaGetSymbolAddress((void**)&bfB_p, g_bfB_p);
    cudaGetSymbolAddress((void**)&agg1, g_agg1);
    cudaGetSymbolAddress((void**)&agg2, g_agg2);
    cudaGetSymbolAddress((void**)&aggp, g_aggp);
    cudaGetSymbolAddress((void**)&rs, g_rs);
    cudaGetSymbolAddress((void**)&wt, g_Wt);
    cudaGetSymbolAddress((void**)&indptr, g_indptr);
    cudaGetSymbolAddress((void**)&cursor, g_cursor);
    cudaGetSymbolAddress((void**)&eidx, g_eidx);
    cudaGetSymbolAddress((void**)&bsum, g_bsum);

    transpose_w9<<<(9 * DIM * DIM + 255) / 256, 256>>>(W1, W2, W3, wt);
    to_bf16<<<(2 * NN * DIM / 4 + 255) / 256, 256>>>(hd0, hp0, bfA_d, bfA_p);

    cudaMemsetAsync(rs, 0, (size_t)6 * NN * sizeof(float), 0);
    int nEmax = nE_ddi > nE_pdi ? nE_ddi : nE_pdi;
    if (nE_ppi > nEmax) nEmax = nE_ppi;
    count2b<<<dim3((nEmax + 255) / 256, 3), 256>>>(
        ddi_s, ddi_d, nE_ddi, pdi_s, pdi_d, nE_pdi, ppi_s, ppi_d, nE_ppi, rs);

    const int nb = (NN + 1023) / 1024;
    const int tb = (NN + 255) / 256;
    scan1<<<dim3(nb, 3), 1024>>>(rs, indptr, bsum);
    scan2<<<3, 256>>>(bsum, nb);
    scan3<<<dim3(tb, 3), 256>>>(rs, indptr, bsum, cursor);

    fill3_kernel<<<dim3((nEmax + 255) / 256, 3), 256>>>(
        ddi_s, ddi_d, nE_ddi, pdi_s, pdi_d, nE_pdi, ppi_s, ppi_d, nE_ppi, cursor, eidx);

    rsqrt_kernel<<<(6 * NN + 255) / 256, 256>>>(rs, 6 * NN);

    float* outd = (float*)d_out;
    float* outp = outd + (size_t)NDRUG * DIM;

    // layer 1: A(bf16 inputs) -> B(bf16), ReLU
    launch_layer<true, true>(bfA_d, bfA_p, bfB_d, bfB_p,
                             wt + 0 * 3 * DIM * DIM, b1, indptr, eidx, agg1, agg2, aggp, rs);
    // layer 2: B -> A(bf16), ReLU
    launch_layer<true, true>(bfB_d, bfB_p, bfA_d, bfA_p,
                             wt + 1 * 3 * DIM * DIM, b2, indptr, eidx, agg1, agg2, aggp, rs);
    // layer 3: A -> d_out (fp32), no activation
    launch_layer<false, false>(bfA_d, bfA_p, outd, outp,
                               wt + 2 * 3 * DIM * DIM, b3, indptr, eidx, agg1, agg2, aggp, rs);
}